// round 1
// baseline (speedup 1.0000x reference)
#include <cuda_runtime.h>
#include <cstdint>

// Problem constants (fixed shapes for SparseMPNN_30709016166923)
#define B_ 2
#define N_ 40000
#define E_ 640000
#define H_ 4
#define F_ 32
#define HF_ 128           // H*F
#define NEG_SLOPE 0.2f

// Scratch (allocation-free rule: __device__ globals)
__device__ float    d_eself[B_ * N_ * H_];   // [B,N,H]
__device__ float    d_eadjc[B_ * N_ * H_];
__device__ unsigned d_m1key[B_ * N_ * H_];   // seg-max of leaky-relu logits, order-preserving uint key

__device__ __forceinline__ unsigned fkey(float f) {
    unsigned u = __float_as_uint(f);
    return (u & 0x80000000u) ? ~u : (u | 0x80000000u);
}
__device__ __forceinline__ float funkey(unsigned k) {
    return __uint_as_float((k & 0x80000000u) ? (k ^ 0x80000000u) : ~k);
}
__device__ __forceinline__ float lrelu(float x) {
    return x > 0.0f ? x : NEG_SLOPE * x;
}

// K1: per-node logits e_self/e_adjc = <X[b,n,h,:], A[h,:]>; also zero-init m1key.
// One warp per (b,n). lane -> (h = lane>>3, j = lane&7), each lane dots 4 floats.
__global__ void k1_node_logits(const float* __restrict__ X,
                               const float* __restrict__ As,
                               const float* __restrict__ Aa) {
    int warp = (blockIdx.x * blockDim.x + threadIdx.x) >> 5;
    int lane = threadIdx.x & 31;
    if (warp >= B_ * N_) return;

    float4 x  = __ldg((const float4*)(X) + (size_t)warp * (HF_ / 4) + lane);
    int h = lane >> 3, j = lane & 7;
    float4 as = __ldg((const float4*)(As) + h * 8 + j);
    float4 aa = __ldg((const float4*)(Aa) + h * 8 + j);

    float ds = x.x * as.x + x.y * as.y + x.z * as.z + x.w * as.w;
    float da = x.x * aa.x + x.y * aa.y + x.z * aa.z + x.w * aa.w;
    // reduce within each octet (same h)
    #pragma unroll
    for (int m = 1; m < 8; m <<= 1) {
        ds += __shfl_xor_sync(0xFFFFFFFFu, ds, m);
        da += __shfl_xor_sync(0xFFFFFFFFu, da, m);
    }
    if (j == 0) {
        int o = warp * H_ + h;
        d_eself[o] = ds;
        d_eadjc[o] = da;
        d_m1key[o] = 0u;  // < fkey(any finite float); empty segments never read
    }
}

// K2: per-edge segmented max of leaky_relu(e_self[t] + e_adjc[s]) into m1key.
__global__ void k2_edge_max(const int* __restrict__ tg, const int* __restrict__ sc) {
    int i = blockIdx.x * blockDim.x + threadIdx.x;  // b*E + e
    if (i >= B_ * E_) return;
    int b = i / E_;
    int t = tg[i], s = sc[i];
    const float4 es = *(const float4*)(d_eself + ((size_t)b * N_ + t) * H_);
    const float4 ea = *(const float4*)(d_eadjc + ((size_t)b * N_ + s) * H_);
    unsigned* mk = d_m1key + ((size_t)b * N_ + t) * H_;
    atomicMax(mk + 0, fkey(lrelu(es.x + ea.x)));
    atomicMax(mk + 1, fkey(lrelu(es.y + ea.y)));
    atomicMax(mk + 2, fkey(lrelu(es.z + ea.z)));
    atomicMax(mk + 3, fkey(lrelu(es.w + ea.w)));
}

// K3: per-edge attn = exp(e - m1[t]) (m2 == 1 exactly; 1+1e-9 == 1.0f),
// msg = attn * X[b,s,:,:], scatter-add into out[b,t,:,:].
// One warp per edge; lane handles 4 contiguous floats (h = lane>>3).
__global__ void k3_scatter(const float* __restrict__ X,
                           const int* __restrict__ tg,
                           const int* __restrict__ sc,
                           float* __restrict__ out) {
    int gw = (blockIdx.x * blockDim.x + threadIdx.x) >> 5;
    int lane = threadIdx.x & 31;
    if (gw >= B_ * E_) return;
    int b = gw / E_;
    int t = tg[gw], s = sc[gw];
    int h = lane >> 3;

    size_t tb = ((size_t)b * N_ + t) * H_ + h;
    size_t sb = ((size_t)b * N_ + s) * H_ + h;
    float e  = lrelu(d_eself[tb] + d_eadjc[sb]);
    float m1 = funkey(d_m1key[tb]);
    float attn = __expf(e - m1);

    float4 x = __ldg((const float4*)(X) + ((size_t)b * N_ + s) * (HF_ / 4) + lane);
    float* o = out + (((size_t)b * N_ + t) * HF_) + lane * 4;
    float v0 = attn * x.x, v1 = attn * x.y, v2 = attn * x.z, v3 = attn * x.w;
    asm volatile("red.global.add.v4.f32 [%0], {%1, %2, %3, %4};"
                 :: "l"(o), "f"(v0), "f"(v1), "f"(v2), "f"(v3)
                 : "memory");
}

extern "C" void kernel_launch(void* const* d_in, const int* in_sizes, int n_in,
                              void* d_out, int out_size) {
    const float* X  = (const float*)d_in[0];   // [B,N,H,F]
    const float* As = (const float*)d_in[1];   // [H,F]
    const float* Aa = (const float*)d_in[2];   // [H,F]
    // d_in[3] = degree (unused by reference)
    const int* tg = (const int*)d_in[4];       // [B,E]
    const int* sc = (const int*)d_in[5];       // [B,E]
    float* out = (float*)d_out;                // [B,N,H,F]
    (void)in_sizes; (void)n_in;

    cudaMemsetAsync(out, 0, (size_t)out_size * sizeof(float), 0);

    {   // K1: B*N warps
        int warps = B_ * N_;
        int threads = 256;
        int blocks = (warps * 32 + threads - 1) / threads;
        k1_node_logits<<<blocks, threads>>>(X, As, Aa);
    }
    {   // K2: B*E threads
        int n = B_ * E_;
        int threads = 256;
        int blocks = (n + threads - 1) / threads;
        k2_edge_max<<<blocks, threads>>>(tg, sc);
    }
    {   // K3: B*E warps
        long long warps = (long long)B_ * E_;
        int threads = 256;
        long long blocks = (warps * 32 + threads - 1) / threads;
        k3_scatter<<<(unsigned)blocks, threads>>>(X, tg, sc, out);
    }
}

// round 2
// speedup vs baseline: 1.9139x; 1.9139x over previous
#include <cuda_runtime.h>
#include <cstdint>
#include <math_constants.h>

// Fixed shapes for SparseMPNN_30709016166923
#define B_ 2
#define N_ 40000
#define E_ 640000
#define H_ 4
#define F_ 32
#define HF_ 128
#define NB_ (B_ * N_)          // 80000 segments (b, target-node)
#define NE_ (B_ * E_)          // 1280000 edges
#define NEG_SLOPE 0.2f

#define SCAN_BLK 1024
#define NBLK ((NB_ + SCAN_BLK - 1) / SCAN_BLK)   // 79

// Scratch (__device__ globals; no allocations allowed)
__device__ float d_eself[NB_ * H_];
__device__ float d_eadjc[NB_ * H_];
__device__ int   d_cnt[NB_];       // per-segment edge count
__device__ int   d_rowp[NB_];      // exclusive prefix (row start)
__device__ int   d_cursor[NB_];    // fill cursors
__device__ int   d_bsum[NBLK];
__device__ int   d_boff[NBLK];
__device__ int   d_srcl[NE_];      // CSR: source node id per edge slot

__device__ __forceinline__ float lrelu(float x) {
    return x > 0.0f ? x : NEG_SLOPE * x;
}

// K1: per-node logits; one warp per (b,n); also zero d_cnt.
__global__ void k1_node_logits(const float* __restrict__ X,
                               const float* __restrict__ As,
                               const float* __restrict__ Aa) {
    int warp = (blockIdx.x * blockDim.x + threadIdx.x) >> 5;
    int lane = threadIdx.x & 31;
    if (warp >= NB_) return;

    float4 x  = __ldg((const float4*)(X) + (size_t)warp * (HF_ / 4) + lane);
    int h = lane >> 3, j = lane & 7;
    float4 as = __ldg((const float4*)(As) + h * 8 + j);
    float4 aa = __ldg((const float4*)(Aa) + h * 8 + j);

    float ds = x.x * as.x + x.y * as.y + x.z * as.z + x.w * as.w;
    float da = x.x * aa.x + x.y * aa.y + x.z * aa.z + x.w * aa.w;
    #pragma unroll
    for (int m = 1; m < 8; m <<= 1) {
        ds += __shfl_xor_sync(0xFFFFFFFFu, ds, m);
        da += __shfl_xor_sync(0xFFFFFFFFu, da, m);
    }
    if (j == 0) {
        int o = warp * H_ + h;
        d_eself[o] = ds;
        d_eadjc[o] = da;
    }
    if (lane == 0) d_cnt[warp] = 0;
}

// K2a: count edges per (b, target)
__global__ void ka_count(const int* __restrict__ tg) {
    int i = blockIdx.x * blockDim.x + threadIdx.x;
    if (i >= NE_) return;
    int b = i / E_;
    atomicAdd(&d_cnt[b * N_ + tg[i]], 1);
}

// Scan stage 1: per-block exclusive scan + block totals
__global__ void scan_a() {
    __shared__ int sm[SCAN_BLK];
    int t = threadIdx.x;
    int i = blockIdx.x * SCAN_BLK + t;
    int v = (i < NB_) ? d_cnt[i] : 0;
    sm[t] = v;
    __syncthreads();
    #pragma unroll
    for (int off = 1; off < SCAN_BLK; off <<= 1) {
        int u = (t >= off) ? sm[t - off] : 0;
        __syncthreads();
        sm[t] += u;
        __syncthreads();
    }
    if (i < NB_) d_rowp[i] = sm[t] - v;   // exclusive
    if (t == SCAN_BLK - 1) d_bsum[blockIdx.x] = sm[t];
}

// Scan stage 2: scan the 79 block sums (single block)
__global__ void scan_b() {
    __shared__ int sm[128];
    int t = threadIdx.x;
    int v = (t < NBLK) ? d_bsum[t] : 0;
    sm[t] = v;
    __syncthreads();
    #pragma unroll
    for (int off = 1; off < 128; off <<= 1) {
        int u = (t >= off) ? sm[t - off] : 0;
        __syncthreads();
        sm[t] += u;
        __syncthreads();
    }
    if (t < NBLK) d_boff[t] = sm[t] - v;  // exclusive
}

// Scan stage 3: add block offsets; init cursors
__global__ void scan_c() {
    int i = blockIdx.x * blockDim.x + threadIdx.x;
    if (i >= NB_) return;
    int r = d_rowp[i] + d_boff[i >> 10];
    d_rowp[i] = r;
    d_cursor[i] = r;
}

// Fill CSR source list
__global__ void kc_fill(const int* __restrict__ tg, const int* __restrict__ sc) {
    int i = blockIdx.x * blockDim.x + threadIdx.x;
    if (i >= NE_) return;
    int b = i / E_;
    int pos = atomicAdd(&d_cursor[b * N_ + tg[i]], 1);
    d_srcl[pos] = sc[i];
}

// K3: one warp per (b, target). Single pass:
//   acc = sum_k exp(e_k) * X[src_k];  m = max e_k;  out = exp(-m) * acc
// (reference's m2 normalization == 1.0 exactly in fp32; degree unused)
__global__ void k3_gather(const float* __restrict__ X, float* __restrict__ out) {
    int w = (blockIdx.x * blockDim.x + threadIdx.x) >> 5;
    int lane = threadIdx.x & 31;
    if (w >= NB_) return;

    int len = d_cnt[w];
    float4* o = (float4*)out + (size_t)w * (HF_ / 4) + lane;
    if (len == 0) {
        *o = make_float4(0.f, 0.f, 0.f, 0.f);
        return;
    }
    int start = d_rowp[w];
    int b = w / N_;
    int h = lane >> 3;
    size_t bbase = (size_t)b * N_;

    float esh = d_eself[w * H_ + h];
    float mx = -CUDART_INF_F;
    float a0 = 0.f, a1 = 0.f, a2 = 0.f, a3 = 0.f;

    const int* sl = d_srcl + start;
    int s = __ldg(sl);
    for (int k = 0; k < len; k++) {
        int s_nxt = (k + 1 < len) ? __ldg(sl + k + 1) : 0;
        float eah = __ldg(d_eadjc + (bbase + s) * H_ + h);
        float4 x = __ldg((const float4*)X + (bbase + s) * (HF_ / 4) + lane);
        float e = lrelu(esh + eah);
        float wt = __expf(e);
        mx = fmaxf(mx, e);
        a0 = fmaf(wt, x.x, a0);
        a1 = fmaf(wt, x.y, a1);
        a2 = fmaf(wt, x.z, a2);
        a3 = fmaf(wt, x.w, a3);
        s = s_nxt;
    }
    float scl = __expf(-mx);
    *o = make_float4(a0 * scl, a1 * scl, a2 * scl, a3 * scl);
}

extern "C" void kernel_launch(void* const* d_in, const int* in_sizes, int n_in,
                              void* d_out, int out_size) {
    const float* X  = (const float*)d_in[0];   // [B,N,H,F]
    const float* As = (const float*)d_in[1];   // [H,F]
    const float* Aa = (const float*)d_in[2];   // [H,F]
    // d_in[3] = degree (unused by reference)
    const int* tg = (const int*)d_in[4];       // [B,E]
    const int* sc = (const int*)d_in[5];       // [B,E]
    float* out = (float*)d_out;                // [B,N,H,F]
    (void)in_sizes; (void)n_in; (void)out_size;

    k1_node_logits<<<(NB_ * 32 + 255) / 256, 256>>>(X, As, Aa);
    ka_count<<<(NE_ + 255) / 256, 256>>>(tg);
    scan_a<<<NBLK, SCAN_BLK>>>();
    scan_b<<<1, 128>>>();
    scan_c<<<(NB_ + 255) / 256, 256>>>();
    kc_fill<<<(NE_ + 255) / 256, 256>>>(tg, sc);
    k3_gather<<<(NB_ * 32 + 255) / 256, 256>>>(X, out);
}